// round 11
// baseline (speedup 1.0000x reference)
#include <cuda_runtime.h>
#include <cuda_bf16.h>
#include <cstdint>

typedef unsigned int  u32;
typedef unsigned char uc;

// Problem constants: B=1024, FANOUTS=[10,25], DIM=256, N_NODES=100000
#define TM      32
#define PITCHB  528                 // 264 bf16 per row (bank-conflict-free)
#define XBUF    (TM * PITCHB)       // 16896 B
#define SMEMSZ  (4 * XBUF)          // Xs_hi, Xs_lo, Xn_hi, Xn_lo = 67584 B

// Scratch (device globals; allocation-free per harness rules)
__device__ float g_n1[10240 * 256];
__device__ float g_n0[1024  * 256];
// W split+transposed: [layer][c][k] bf16, c in [0,256): 0-127 self, 128-255 neigh
__device__ __nv_bfloat16 g_Wh[2][256 * 256];
__device__ __nv_bfloat16 g_Wl[2][256 * 256];

__device__ __forceinline__ void split2(float x0, float x1, u32& h, u32& l) {
    __nv_bfloat16 h0 = __float2bfloat16_rn(x0);
    __nv_bfloat16 h1 = __float2bfloat16_rn(x1);
    __nv_bfloat16 l0 = __float2bfloat16_rn(x0 - __bfloat162float(h0));
    __nv_bfloat16 l1 = __float2bfloat16_rn(x1 - __bfloat162float(h1));
    __nv_bfloat162 H; H.x = h0; H.y = h1;     // .x = low 16 bits
    __nv_bfloat162 L; L.x = l0; L.y = l1;
    h = *reinterpret_cast<u32*>(&H);
    l = *reinterpret_cast<u32*>(&L);
}

__device__ __forceinline__ void mma16816(
    float* d, u32 a0, u32 a1, u32 a2, u32 a3, u32 b0, u32 b1)
{
    asm volatile(
        "mma.sync.aligned.m16n8k16.row.col.f32.bf16.bf16.f32 "
        "{%0,%1,%2,%3}, {%4,%5,%6,%7}, {%8,%9}, {%0,%1,%2,%3};"
        : "+f"(d[0]), "+f"(d[1]), "+f"(d[2]), "+f"(d[3])
        : "r"(a0), "r"(a1), "r"(a2), "r"(a3), "r"(b0), "r"(b1));
}

// Pack W hi/lo, transposed to [c][k]. Reads coalesced over c.
__global__ void __launch_bounds__(512)
pack_w(const float* __restrict__ W0s, const float* __restrict__ W0n,
       const float* __restrict__ W1s, const float* __restrict__ W1n)
{
    const int i = blockIdx.x * 512 + threadIdx.x;   // 131072 total
    const int l = i >> 16, r = i & 65535;
    const int k = r >> 8, c = r & 255;
    const float* Ws = l ? W1s : W0s;
    const float* Wn = l ? W1n : W0n;
    const float v = (c < 128) ? __ldg(Ws + k * 128 + c)
                              : __ldg(Wn + k * 128 + (c - 128));
    const __nv_bfloat16 h  = __float2bfloat16_rn(v);
    const __nv_bfloat16 lo = __float2bfloat16_rn(v - __bfloat162float(h));
    g_Wh[l][c * 256 + k] = h;
    g_Wl[l][c * 256 + k] = lo;
}

// One tile of TM=32 rows, 256 threads (8 warps):
//   Xs[r] = ssrc[ sidx? sidx[row] : row ]          (fp32 -> bf16 hi/lo)
//   Xn[r] = mean_{j<F} nsrc[ nidx? nidx[row*F+j] : row*F+j ]
//   out[row][c] = act( (c<128 ? Xs@Ws : Xn@Wn)[c] )  via mma.sync error-split
template <int F, bool RELU, bool IDX>
__device__ __forceinline__ void sage_mma_tile(
    const float4* __restrict__ ssrc4, const float4* __restrict__ nsrc4,
    const int* __restrict__ sidx, const int* __restrict__ nidx,
    const __nv_bfloat16* __restrict__ Wh, const __nv_bfloat16* __restrict__ Wl,
    float* __restrict__ out, int m0, uc* smem)
{
    uc* Xsh = smem;
    uc* Xsl = smem + XBUF;
    uc* Xnh = smem + 2 * XBUF;
    uc* Xnl = smem + 3 * XBUF;
    const int tid = threadIdx.x;

    // ---- gather + mean (lane-coalesced), split to bf16 hi/lo in smem ----
    #pragma unroll
    for (int it = 0; it < 8; ++it) {
        const int i = it * 256 + tid;
        const int r = i >> 6, q = i & 63;
        const int row = m0 + r;

        const int gs = IDX ? __ldg(sidx + row) : row;
        const float4 s = __ldcg(ssrc4 + (size_t)gs * 64 + q);

        float4 a0 = make_float4(0.f, 0.f, 0.f, 0.f), a1 = a0;
        const size_t nb = (size_t)row * F;
        #pragma unroll
        for (int j = 0; j < F; j += 2) {
            const size_t g0 = IDX ? (size_t)__ldg(nidx + nb + j) : nb + j;
            const float4 v = __ldcg(nsrc4 + g0 * 64 + q);
            a0.x += v.x; a0.y += v.y; a0.z += v.z; a0.w += v.w;
            if (j + 1 < F) {
                const size_t g1 = IDX ? (size_t)__ldg(nidx + nb + j + 1) : nb + j + 1;
                const float4 w = __ldcg(nsrc4 + g1 * 64 + q);
                a1.x += w.x; a1.y += w.y; a1.z += w.z; a1.w += w.w;
            }
        }
        const float inv = 1.0f / (float)F;
        const float nx = (a0.x + a1.x) * inv, ny = (a0.y + a1.y) * inv;
        const float nz = (a0.z + a1.z) * inv, nw = (a0.w + a1.w) * inv;

        u32 h01, l01, h23, l23;
        split2(s.x, s.y, h01, l01); split2(s.z, s.w, h23, l23);
        *(uint2*)(Xsh + r * PITCHB + q * 8) = make_uint2(h01, h23);
        *(uint2*)(Xsl + r * PITCHB + q * 8) = make_uint2(l01, l23);
        split2(nx, ny, h01, l01); split2(nz, nw, h23, l23);
        *(uint2*)(Xnh + r * PITCHB + q * 8) = make_uint2(h01, h23);
        *(uint2*)(Xnl + r * PITCHB + q * 8) = make_uint2(l01, l23);
    }
    __syncthreads();

    // ---- GEMM: warp (mb, nq) -> rows [mb*16,+16) x cols [nq*64,+64) ----
    const int wid = tid >> 5, lane = tid & 31;
    const int mb = wid >> 2, nq = wid & 3;
    const int gid = lane >> 2, tig = lane & 3;
    const uc* Xh = (nq < 2) ? Xsh : Xnh;          // warp-uniform
    const uc* Xl = (nq < 2) ? Xsl : Xnl;
    const int rbase = mb * 16 + gid;

    float d[8][4];
    #pragma unroll
    for (int nt = 0; nt < 8; ++nt)
        d[nt][0] = d[nt][1] = d[nt][2] = d[nt][3] = 0.f;

    const __nv_bfloat16* WhB = Wh + (nq * 64 + gid) * 256 + 2 * tig;
    const __nv_bfloat16* WlB = Wl + (nq * 64 + gid) * 256 + 2 * tig;

    #pragma unroll 1
    for (int kb = 0; kb < 16; ++kb) {
        const uc* pa = Xh + rbase * PITCHB + (kb * 16 + 2 * tig) * 2;
        const u32 ah0 = *(const u32*)(pa);
        const u32 ah1 = *(const u32*)(pa + 8 * PITCHB);
        const u32 ah2 = *(const u32*)(pa + 16);
        const u32 ah3 = *(const u32*)(pa + 8 * PITCHB + 16);
        const uc* pl = Xl + rbase * PITCHB + (kb * 16 + 2 * tig) * 2;
        const u32 al0 = *(const u32*)(pl);
        const u32 al1 = *(const u32*)(pl + 8 * PITCHB);
        const u32 al2 = *(const u32*)(pl + 16);
        const u32 al3 = *(const u32*)(pl + 8 * PITCHB + 16);

        #pragma unroll
        for (int nt = 0; nt < 8; ++nt) {
            const __nv_bfloat16* wh = WhB + nt * 8 * 256 + kb * 16;
            const __nv_bfloat16* wl = WlB + nt * 8 * 256 + kb * 16;
            const u32 bh0 = *(const u32*)(wh);
            const u32 bh1 = *(const u32*)(wh + 8);
            const u32 bl0 = *(const u32*)(wl);
            const u32 bl1 = *(const u32*)(wl + 8);
            mma16816(d[nt], ah0, ah1, ah2, ah3, bh0, bh1);   // hi*hi
            mma16816(d[nt], ah0, ah1, ah2, ah3, bl0, bl1);   // hi*lo
            mma16816(d[nt], al0, al1, al2, al3, bh0, bh1);   // lo*hi
        }
    }

    // ---- epilogue: fragment rows (gid, gid+8), cols 2*tig+{0,1} ----
    const int grow = m0 + rbase;
    #pragma unroll
    for (int nt = 0; nt < 8; ++nt) {
        const int col = nq * 64 + nt * 8 + 2 * tig;
        float2 v0 = make_float2(d[nt][0], d[nt][1]);
        float2 v1 = make_float2(d[nt][2], d[nt][3]);
        if (RELU) {
            v0.x = fmaxf(v0.x, 0.f); v0.y = fmaxf(v0.y, 0.f);
            v1.x = fmaxf(v1.x, 0.f); v1.y = fmaxf(v1.y, 0.f);
        }
        *(float2*)(out + (size_t)grow * 256 + col)       = v0;
        *(float2*)(out + (size_t)(grow + 8) * 256 + col) = v1;
    }
}

extern __shared__ uc smem_u[];

// K1: layer 0. blocks [0,320): n1 tiles (F=25); [320,352): n0 tiles (F=10).
__global__ void __launch_bounds__(256, 3)
sage_layer0_kernel(const float4* __restrict__ feat4,
                   const int* __restrict__ sn0,
                   const int* __restrict__ sn1,
                   const int* __restrict__ sn2)
{
    if (blockIdx.x < 320) {
        sage_mma_tile<25, true, true>(feat4, feat4, sn1, sn2,
            g_Wh[0], g_Wl[0], g_n1, blockIdx.x * TM, smem_u);
    } else {
        sage_mma_tile<10, true, true>(feat4, feat4, sn0, sn1,
            g_Wh[0], g_Wl[0], g_n0, (blockIdx.x - 320) * TM, smem_u);
    }
}

// K2: layer 1 (no activation): self = n0 row, neigh = mean10 of contiguous
// n1 rows. 1024 rows / 32 -> 32 CTAs.
__global__ void __launch_bounds__(256, 3)
sage_layer1_kernel(float* __restrict__ out)
{
    sage_mma_tile<10, false, false>(
        (const float4*)g_n0, (const float4*)g_n1, nullptr, nullptr,
        g_Wh[1], g_Wl[1], out, blockIdx.x * TM, smem_u);
}

// =============================================================================
extern "C" void kernel_launch(void* const* d_in, const int* in_sizes, int n_in,
                              void* d_out, int out_size)
{
    const float4* feat4 = (const float4*)d_in[0];
    const int*    sn0   = (const int*)  d_in[1];
    const int*    sn1   = (const int*)  d_in[2];
    const int*    sn2   = (const int*)  d_in[3];
    const float*  W0s   = (const float*)d_in[4];
    const float*  W0n   = (const float*)d_in[5];
    const float*  W1s   = (const float*)d_in[6];
    const float*  W1n   = (const float*)d_in[7];
    float*        out   = (float*)      d_out;

    static bool attr_set = false;
    if (!attr_set) {
        cudaFuncSetAttribute(sage_layer0_kernel,
                             cudaFuncAttributeMaxDynamicSharedMemorySize, SMEMSZ);
        cudaFuncSetAttribute(sage_layer1_kernel,
                             cudaFuncAttributeMaxDynamicSharedMemorySize, SMEMSZ);
        attr_set = true;
    }

    pack_w<<<256, 512>>>(W0s, W0n, W1s, W1n);
    sage_layer0_kernel<<<352, 256, SMEMSZ>>>(feat4, sn0, sn1, sn2);
    sage_layer1_kernel<<<32, 256, SMEMSZ>>>(out);
}